// round 3
// baseline (speedup 1.0000x reference)
#include <cuda_runtime.h>
#include <cstddef>

#define TSTEPS 512
#define BATCH  512
#define NUDIM  64
#define NXDIM  128
#define NVDIM  256
#define NYDIM  64
#define RPC    4
#define NCTA   (BATCH / RPC)
#define NTHR   256

// ---------------- transposed weights (built once per launch by prep_kernel) ----
// g_MT[k * Rout + j] = M[j][k]
__device__ float g_AT [NXDIM * NXDIM];
__device__ float g_B1T[NVDIM * NXDIM];
__device__ float g_B2T[NUDIM * NXDIM];
__device__ float g_C1T[NXDIM * NVDIM];
__device__ float g_C2T[NXDIM * NYDIM];
__device__ float g_D11T[NVDIM * NVDIM];
__device__ float g_D12T[NUDIM * NVDIM];
__device__ float g_D21T[NVDIM * NYDIM];
__device__ float g_D22T[NUDIM * NYDIM];

// dst[k*J + j] = src[j*K + k]; dst index == flat id within segment.
__global__ void prep_kernel(const float* __restrict__ A,  const float* __restrict__ B1,
                            const float* __restrict__ B2, const float* __restrict__ C1,
                            const float* __restrict__ C2, const float* __restrict__ D11,
                            const float* __restrict__ D12,const float* __restrict__ D21,
                            const float* __restrict__ D22)
{
    int id = blockIdx.x * blockDim.x + threadIdx.x;
    int off = 0;
#define XPOSE(dst, src, J, K)                                              \
    if (id < off + (J) * (K)) {                                            \
        int i = id - off; int k = i / (J); int j = i % (J);                \
        dst[i] = src[(size_t)j * (K) + k]; return;                         \
    } off += (J) * (K);
    XPOSE(g_AT,   A,   NXDIM, NXDIM)
    XPOSE(g_B1T,  B1,  NXDIM, NVDIM)
    XPOSE(g_B2T,  B2,  NXDIM, NUDIM)
    XPOSE(g_C1T,  C1,  NVDIM, NXDIM)
    XPOSE(g_C2T,  C2,  NYDIM, NXDIM)
    XPOSE(g_D11T, D11, NVDIM, NVDIM)
    XPOSE(g_D12T, D12, NVDIM, NUDIM)
    XPOSE(g_D21T, D21, NYDIM, NVDIM)
    XPOSE(g_D22T, D22, NYDIM, NUDIM)
#undef XPOSE
}

// ---------------- shared memory ----------------
struct Smem {
    float  C1T [NXDIM * NVDIM];   // 128 KB, staged
    float  D12T[NUDIM * NVDIM];   //  64 KB, staged
    float  D22T[NUDIM * NYDIM];   //  16 KB, staged
    float4 xk[2][NXDIM];          // state, float4 across the 4 rows
    float4 w[NVDIM];              // equilibrium solution
    float4 uu[NUDIM];             // current input tile
    float4 bblk[32];              // handoff for panel being solved
    float  diagc[8][4][32];       // packed 8x8 strictly-lower coefs (28 used)
    float4 xpart[NXDIM];          // phase-C x partials
    float4 ypart[3][NYDIM];       // phase-C y partials (quarters 1..3)
};

#define FMA4(a0,a1,a2,a3,c,v) do { \
    a0 = fmaf((c), (v).x, a0); a1 = fmaf((c), (v).y, a1); \
    a2 = fmaf((c), (v).z, a2); a3 = fmaf((c), (v).w, a3); } while (0)

__global__ void __launch_bounds__(NTHR, 1)
ren_kernel(const float* __restrict__ x0, const float* __restrict__ u,
           const float* __restrict__ D11,
           const float* __restrict__ bx, const float* __restrict__ bv,
           const float* __restrict__ by, float* __restrict__ out)
{
    extern __shared__ char smem_raw[];
    Smem& s = *reinterpret_cast<Smem*>(smem_raw);
    const int tid  = threadIdx.x;
    const int lane = tid & 31;
    const int wid  = tid >> 5;
    const int row0 = blockIdx.x * RPC;

    // ---- one-time staging ----
    for (int i = tid; i < NXDIM * NVDIM; i += NTHR) s.C1T[i]  = g_C1T[i];
    for (int i = tid; i < NUDIM * NVDIM; i += NTHR) s.D12T[i] = g_D12T[i];
    for (int i = tid; i < NUDIM * NYDIM; i += NTHR) s.D22T[i] = g_D22T[i];
    if (tid < 32) {                       // packed 8x8 strictly-lower blocks of D11
        int blk = tid >> 2, g = tid & 3;
        int base = blk * 32 + g * 8, idx = 0;
        for (int ii = 1; ii < 8; ii++)
            for (int jj = 0; jj < ii; jj++)
                s.diagc[blk][g][idx++] = D11[(size_t)(base + ii) * NVDIM + (base + jj)];
    }
    for (int i = tid; i < RPC * NXDIM; i += NTHR) {   // initial state
        int r = i >> 7, k = i & 127;
        ((float*)s.xk[0])[k * 4 + r] = x0[(size_t)(row0 + r) * NXDIM + k];
    }
    const float bvr = bv[tid];
    const float bxr = bx[tid & 127];
    const float byr = by[tid & 63];

    // diag coefficient columns dc[j] = D11[lane][j] for panel 0 (warps 0..3 only)
    float dc[32];
    if (wid < RPC) {
#pragma unroll
        for (int j = 0; j < 32; j++)
            dc[j] = g_D11T[(size_t)j * NVDIM + lane];
    }
    __syncthreads();

    float* yout = out + (size_t)BATCH * NXDIM;
    int cur = 0;

    for (int t = 0; t < TSTEPS; t++) {
        // ---- load u tile (coalesced) ----
        {
            int r = tid >> 6, k = tid & 63;
            ((float*)s.uu)[k * 4 + r] =
                u[((size_t)t * BATCH + row0 + r) * NUDIM + k];
        }
        __syncthreads();
        const int nxt = cur ^ 1;
        const float4* xc = s.xk[cur];

        // ---- phase A: b = bv + C1 x + D12 u (thread = v-feature, 4 rows) ----
        float ba0 = bvr, ba1 = bvr, ba2 = bvr, ba3 = bvr;
#pragma unroll 4
        for (int k = 0; k < NXDIM; k++) {
            float c = s.C1T[k * NVDIM + tid];
            float4 v = xc[k];
            FMA4(ba0, ba1, ba2, ba3, c, v);
        }
#pragma unroll 4
        for (int k = 0; k < NUDIM; k++) {
            float c = s.D12T[k * NVDIM + tid];
            float4 v = s.uu[k];
            FMA4(ba0, ba1, ba2, ba3, c, v);
        }

        // ---- phase B: blocked triangular ReLU equilibrium ----
        for (int blk = 0; blk < 8; blk++) {
            const int base = blk * 32;
            if (wid == blk)
                s.bblk[lane] = make_float4(ba0, ba1, ba2, ba3);
            __syncthreads();

            if (wid < RPC) {                      // warp r solves row r
                const int r = wid;
                float bval = ((const float*)s.bblk)[lane * 4 + r];
                float wmine = 0.f;
#pragma unroll
                for (int g = 0; g < 4; g++) {
                    const int q0 = g * 8;
                    float cg[28];
#pragma unroll
                    for (int q = 0; q < 28; q++) cg[q] = s.diagc[blk][g][q];
                    float bg[8];
#pragma unroll
                    for (int q = 0; q < 8; q++)
                        bg[q] = __shfl_sync(0xffffffffu, bval, q0 + q);
                    float wloc[8];
#pragma unroll
                    for (int jj = 0; jj < 8; jj++) {   // redundant serial resolve
                        float wj = fmaxf(bg[jj], 0.f);
                        wloc[jj] = wj;
#pragma unroll
                        for (int ii = jj + 1; ii < 8; ii++)
                            bg[ii] = fmaf(cg[ii * (ii - 1) / 2 + jj], wj, bg[ii]);
                    }
                    if ((lane >> 3) == g) wmine = wloc[lane & 7];
                    // apply group's w to own pre-activation (upper coefs stored as 0)
#pragma unroll
                    for (int jj = 0; jj < 8; jj++)
                        bval = fmaf(dc[q0 + jj], wloc[jj], bval);
                }
                ((float*)s.w)[(base + lane) * 4 + r] = wmine;
                // prefetch next panel's diag columns (wraps for next timestep)
                const int nbase = ((blk + 1) & 7) * 32;
#pragma unroll
                for (int j = 0; j < 32; j++)
                    dc[j] = g_D11T[(size_t)(nbase + j) * NVDIM + (nbase + lane)];
            }
            __syncthreads();

            // rank-32 off-diagonal update for all later features
            if (tid >= base + 32) {
                const float* p = g_D11T + (size_t)base * NVDIM + tid;
#pragma unroll 8
                for (int jj = 0; jj < 32; jj++) {
                    float c = p[(size_t)jj * NVDIM];
                    float4 wv = s.w[base + jj];
                    FMA4(ba0, ba1, ba2, ba3, c, wv);
                }
            }
        }

        // ---- phase C partials (balanced: every thread 896 + 448 FMAs) ----
        const int cj = tid & 127;
        const int ch = tid >> 7;
        float xa0, xa1, xa2, xa3;
        if (ch == 0) { xa0 = bxr; xa1 = bxr; xa2 = bxr; xa3 = bxr; }
        else         { xa0 = 0.f; xa1 = 0.f; xa2 = 0.f; xa3 = 0.f; }
        {
            const int kb = ch * 64;
#pragma unroll 4
            for (int kk = 0; kk < 64; kk++) {
                float a = g_AT[(size_t)(kb + kk) * NXDIM + cj];
                float4 v = xc[kb + kk];
                FMA4(xa0, xa1, xa2, xa3, a, v);
            }
        }
        {
            const int kb = ch * 128;
#pragma unroll 4
            for (int kk = 0; kk < 128; kk++) {
                float a = g_B1T[(size_t)(kb + kk) * NXDIM + cj];
                float4 v = s.w[kb + kk];
                FMA4(xa0, xa1, xa2, xa3, a, v);
            }
        }
        {
            const int kb = ch * 32;
#pragma unroll 4
            for (int kk = 0; kk < 32; kk++) {
                float a = g_B2T[(size_t)(kb + kk) * NXDIM + cj];
                float4 v = s.uu[kb + kk];
                FMA4(xa0, xa1, xa2, xa3, a, v);
            }
        }
        if (ch == 1) s.xpart[cj] = make_float4(xa0, xa1, xa2, xa3);

        // y: 4 k-quarters, one per 64-thread group
        const int yj = tid & 63;
        const int yq = tid >> 6;
        float ya0, ya1, ya2, ya3;
        if (yq == 0) { ya0 = byr; ya1 = byr; ya2 = byr; ya3 = byr; }
        else         { ya0 = 0.f; ya1 = 0.f; ya2 = 0.f; ya3 = 0.f; }
        {
            const int kb = yq * 32;
#pragma unroll 4
            for (int kk = 0; kk < 32; kk++) {
                float a = g_C2T[(size_t)(kb + kk) * NYDIM + yj];
                float4 v = xc[kb + kk];
                FMA4(ya0, ya1, ya2, ya3, a, v);
            }
        }
        {
            const int kb = yq * 64;
#pragma unroll 4
            for (int kk = 0; kk < 64; kk++) {
                float a = g_D21T[(size_t)(kb + kk) * NYDIM + yj];
                float4 v = s.w[kb + kk];
                FMA4(ya0, ya1, ya2, ya3, a, v);
            }
        }
        {
            const int kb = yq * 16;
#pragma unroll 4
            for (int kk = 0; kk < 16; kk++) {
                float a = s.D22T[(kb + kk) * NYDIM + yj];
                float4 v = s.uu[kb + kk];
                FMA4(ya0, ya1, ya2, ya3, a, v);
            }
        }
        if (yq > 0) s.ypart[yq - 1][yj] = make_float4(ya0, ya1, ya2, ya3);
        __syncthreads();

        // ---- combines ----
        if (ch == 0) {
            float4 p = s.xpart[cj];
            xa0 += p.x; xa1 += p.y; xa2 += p.z; xa3 += p.w;
            s.xk[nxt][cj] = make_float4(xa0, xa1, xa2, xa3);
        }
        if (yq == 0) {
            float4 p0 = s.ypart[0][yj];
            float4 p1 = s.ypart[1][yj];
            float4 p2 = s.ypart[2][yj];
            ya0 += p0.x + p1.x + p2.x;
            ya1 += p0.y + p1.y + p2.y;
            ya2 += p0.z + p1.z + p2.z;
            ya3 += p0.w + p1.w + p2.w;
            float* yo = yout + ((size_t)t * BATCH + row0) * NYDIM + yj;
            yo[0 * NYDIM] = ya0;
            yo[1 * NYDIM] = ya1;
            yo[2 * NYDIM] = ya2;
            yo[3 * NYDIM] = ya3;
        }
        cur ^= 1;
    }

    // ---- final state x1 ----
    __syncthreads();
    if (tid < NXDIM) {
        float4 v = s.xk[cur][tid];
        out[(size_t)(row0 + 0) * NXDIM + tid] = v.x;
        out[(size_t)(row0 + 1) * NXDIM + tid] = v.y;
        out[(size_t)(row0 + 2) * NXDIM + tid] = v.z;
        out[(size_t)(row0 + 3) * NXDIM + tid] = v.w;
    }
}

extern "C" void kernel_launch(void* const* d_in, const int* in_sizes, int n_in,
                              void* d_out, int out_size)
{
    const float* x0  = (const float*)d_in[0];
    const float* u   = (const float*)d_in[1];
    const float* A   = (const float*)d_in[2];
    const float* B1  = (const float*)d_in[3];
    const float* B2  = (const float*)d_in[4];
    const float* C1  = (const float*)d_in[5];
    const float* C2  = (const float*)d_in[6];
    const float* D11 = (const float*)d_in[7];
    const float* D12 = (const float*)d_in[8];
    const float* D21 = (const float*)d_in[9];
    const float* D22 = (const float*)d_in[10];
    const float* bx  = (const float*)d_in[11];
    const float* bv  = (const float*)d_in[12];
    const float* by  = (const float*)d_in[13];
    float* out = (float*)d_out;

    // 200704 transposed elements total
    prep_kernel<<<784, 256>>>(A, B1, B2, C1, C2, D11, D12, D21, D22);

    size_t smem = sizeof(Smem);
    cudaFuncSetAttribute(ren_kernel, cudaFuncAttributeMaxDynamicSharedMemorySize,
                         (int)smem);
    ren_kernel<<<NCTA, NTHR, smem>>>(x0, u, D11, bx, bv, by, out);
}

// round 4
// speedup vs baseline: 1.8333x; 1.8333x over previous
#include <cuda_runtime.h>
#include <cstddef>

#define TSTEPS 512
#define BATCH  512
#define NUDIM  64
#define NXDIM  128
#define NVDIM  256
#define NYDIM  64
#define RPC    4
#define NCTA   128
#define NTHR   512

// ---------------- packed transposed weights (built once per launch) ----------
// W4[k4 * J + j].q = W[j][4*k4 + q]   (J outputs, K contraction)
__device__ float4 g_C1T4 [32 * NVDIM];
__device__ float4 g_D12T4[16 * NVDIM];
__device__ float4 g_D22T4[16 * NYDIM];
__device__ float4 g_AT4  [32 * NXDIM];
__device__ float4 g_B1T4 [64 * NXDIM];
__device__ float4 g_B2T4 [16 * NXDIM];
__device__ float4 g_C2T4 [32 * NYDIM];
__device__ float4 g_D21T4[64 * NYDIM];
__device__ float4 g_D11P [64 * NVDIM];      // packed D11[j][k] over k (off-diag)
__device__ float  g_D11T [NVDIM * NVDIM];   // scalar D11T[k*256+j] = D11[j][k]

__global__ void prep_kernel(const float* __restrict__ A,  const float* __restrict__ B1,
                            const float* __restrict__ B2, const float* __restrict__ C1,
                            const float* __restrict__ C2, const float* __restrict__ D11,
                            const float* __restrict__ D12,const float* __restrict__ D21,
                            const float* __restrict__ D22)
{
    int id = blockIdx.x * blockDim.x + threadIdx.x;
    int off = 0;
#define XP4(dst, src, J, K)                                                  \
    if (id < off + (J) * (K) / 4) {                                          \
        int i = id - off; int k4 = i / (J); int j = i % (J);                 \
        const float* p = (src) + (size_t)j * (K) + 4 * k4;                   \
        dst[i] = make_float4(p[0], p[1], p[2], p[3]); return;                \
    } off += (J) * (K) / 4;
    XP4(g_C1T4,  C1,  NVDIM, NXDIM)
    XP4(g_D12T4, D12, NVDIM, NUDIM)
    XP4(g_D22T4, D22, NYDIM, NUDIM)
    XP4(g_AT4,   A,   NXDIM, NXDIM)
    XP4(g_B1T4,  B1,  NXDIM, NVDIM)
    XP4(g_B2T4,  B2,  NXDIM, NUDIM)
    XP4(g_C2T4,  C2,  NYDIM, NXDIM)
    XP4(g_D21T4, D21, NYDIM, NVDIM)
    XP4(g_D11P,  D11, NVDIM, NVDIM)
#undef XP4
    if (id < off + NVDIM * NVDIM) {
        int i = id - off; int k = i / NVDIM; int j = i % NVDIM;
        g_D11T[i] = D11[(size_t)j * NVDIM + k];
    }
}

// ---------------- shared memory ----------------
struct Smem {
    float4 C1T4 [32 * NVDIM];     // 128 KB staged
    float4 D12T4[16 * NVDIM];     //  64 KB staged
    float4 xk[2][NXDIM];          // state, float4 across 4 rows
    float4 w[NVDIM];              // equilibrium solution
    float4 uu[2][NUDIM];          // double-buffered input tile
    float  bblk[32][4];           // panel handoff
    float  diagc[8][4][32];       // packed 8x8 strictly-lower coefs
    float4 xpart[3][NXDIM];
    float4 ypart[7][NYDIM];
};

#define FMA4C(acc0,acc1,acc2,acc3,c,v) do {                       \
    acc0 = fmaf((c), (v).x, acc0); acc1 = fmaf((c), (v).y, acc1); \
    acc2 = fmaf((c), (v).z, acc2); acc3 = fmaf((c), (v).w, acc3); } while (0)

__global__ void __launch_bounds__(NTHR, 1)
ren_kernel(const float* __restrict__ x0, const float* __restrict__ u,
           const float* __restrict__ D11,
           const float* __restrict__ bx, const float* __restrict__ bv,
           const float* __restrict__ by, float* __restrict__ out)
{
    extern __shared__ char smem_raw[];
    Smem& s = *reinterpret_cast<Smem*>(smem_raw);
    const int tid  = threadIdx.x;
    const int lane = tid & 31;
    const int wid  = tid >> 5;
    const int row0 = blockIdx.x * RPC;
    const int j    = tid & 255;   // v-feature owned in phases A/B
    const int h    = tid >> 8;    // row-pair (rows 2h, 2h+1)

    // ---- one-time staging ----
    for (int i = tid; i < 32 * NVDIM; i += NTHR) s.C1T4[i]  = g_C1T4[i];
    for (int i = tid; i < 16 * NVDIM; i += NTHR) s.D12T4[i] = g_D12T4[i];
    if (tid < 32) {
        int blk = tid >> 2, g = tid & 3;
        int base = blk * 32 + g * 8, idx = 0;
        for (int ii = 1; ii < 8; ii++)
            for (int jj = 0; jj < ii; jj++)
                s.diagc[blk][g][idx++] = D11[(size_t)(base + ii) * NVDIM + (base + jj)];
    }
    for (int i = tid; i < RPC * NXDIM; i += NTHR) {
        int r = i >> 7, k = i & 127;
        ((float*)s.xk[0])[k * 4 + r] = x0[(size_t)(row0 + r) * NXDIM + k];
    }
    const float bvr = bv[j];
    const float bxr = bx[tid & 127];
    const float byr = by[tid & 63];

    float dc[32];
    if (wid < 4) {
#pragma unroll
        for (int q = 0; q < 32; q++)
            dc[q] = g_D11T[(size_t)q * NVDIM + lane];
    }
    // prefetch u(0)
    float ureg = 0.f;
    if (tid < 256) {
        int r = tid >> 6, k = tid & 63;
        ureg = u[((size_t)0 * BATCH + row0 + r) * NUDIM + k];
    }
    __syncthreads();

    float* yout = out + (size_t)BATCH * NXDIM;
    int cur = 0;

    for (int t = 0; t < TSTEPS; t++) {
        const int ub = t & 1;
        // commit prefetched u(t), issue prefetch of u(t+1)
        if (tid < 256) {
            int r = tid >> 6, k = tid & 63;
            ((float*)s.uu[ub])[k * 4 + r] = ureg;
            int tn = (t + 1 < TSTEPS) ? t + 1 : t;
            ureg = u[((size_t)tn * BATCH + row0 + r) * NUDIM + k];
        }
        __syncthreads();
        const int nxt = cur ^ 1;
        const float4* xc = s.xk[cur];
        const float4* uc = s.uu[ub];

        // ---- phase A: b = bv + C1 x + D12 u  (thread = (feature, row-pair)) --
        float ba0 = bvr, ba1 = bvr;
#pragma unroll 4
        for (int k4 = 0; k4 < 32; k4++) {
            float4 c = s.C1T4[k4 * NVDIM + j];
            const float2* xp = (const float2*)&xc[4 * k4];
            float2 v0 = xp[0 + h], v1 = xp[2 + h], v2 = xp[4 + h], v3 = xp[6 + h];
            ba0 = fmaf(c.x, v0.x, ba0); ba1 = fmaf(c.x, v0.y, ba1);
            ba0 = fmaf(c.y, v1.x, ba0); ba1 = fmaf(c.y, v1.y, ba1);
            ba0 = fmaf(c.z, v2.x, ba0); ba1 = fmaf(c.z, v2.y, ba1);
            ba0 = fmaf(c.w, v3.x, ba0); ba1 = fmaf(c.w, v3.y, ba1);
        }
#pragma unroll 4
        for (int k4 = 0; k4 < 16; k4++) {
            float4 c = s.D12T4[k4 * NVDIM + j];
            const float2* up = (const float2*)&uc[4 * k4];
            float2 v0 = up[0 + h], v1 = up[2 + h], v2 = up[4 + h], v3 = up[6 + h];
            ba0 = fmaf(c.x, v0.x, ba0); ba1 = fmaf(c.x, v0.y, ba1);
            ba0 = fmaf(c.y, v1.x, ba0); ba1 = fmaf(c.y, v1.y, ba1);
            ba0 = fmaf(c.z, v2.x, ba0); ba1 = fmaf(c.z, v2.y, ba1);
            ba0 = fmaf(c.w, v3.x, ba0); ba1 = fmaf(c.w, v3.y, ba1);
        }

        // ---- phase B: blocked triangular ReLU equilibrium ----
        for (int blk = 0; blk < 8; blk++) {
            const int base = blk * 32;
            const bool later = (j >= base + 32);
            if (j >= base && j < base + 32)
                *(float2*)&s.bblk[j - base][2 * h] = make_float2(ba0, ba1);
            // non-solver warps prefetch off-diag coefs; latency hides under solve
            float4 pc[8];
            if (wid >= 4 && later) {
#pragma unroll
                for (int g2 = 0; g2 < 8; g2++)
                    pc[g2] = g_D11P[(blk * 8 + g2) * NVDIM + j];
            }
            __syncthreads();

            if (wid < 4) {                       // warp r solves row r
                const int r = wid;
                float bval = s.bblk[lane][r];
                float wmine = 0.f;
#pragma unroll
                for (int g = 0; g < 4; g++) {
                    const int q0 = g * 8;
                    float cg[28];
#pragma unroll
                    for (int q = 0; q < 28; q++) cg[q] = s.diagc[blk][g][q];
                    float bg[8];
#pragma unroll
                    for (int q = 0; q < 8; q++)
                        bg[q] = __shfl_sync(0xffffffffu, bval, q0 + q);
                    float wloc[8];
#pragma unroll
                    for (int jj = 0; jj < 8; jj++) {   // redundant serial resolve
                        float wj = fmaxf(bg[jj], 0.f);
                        wloc[jj] = wj;
#pragma unroll
                        for (int ii = jj + 1; ii < 8; ii++)
                            bg[ii] = fmaf(cg[ii * (ii - 1) / 2 + jj], wj, bg[ii]);
                    }
                    if ((lane >> 3) == g) wmine = wloc[lane & 7];
                    float a0 = 0.f, a1 = 0.f;      // apply (upper coefs stored 0)
                    a0 = fmaf(dc[q0 + 0], wloc[0], a0); a1 = fmaf(dc[q0 + 1], wloc[1], a1);
                    a0 = fmaf(dc[q0 + 2], wloc[2], a0); a1 = fmaf(dc[q0 + 3], wloc[3], a1);
                    a0 = fmaf(dc[q0 + 4], wloc[4], a0); a1 = fmaf(dc[q0 + 5], wloc[5], a1);
                    a0 = fmaf(dc[q0 + 6], wloc[6], a0); a1 = fmaf(dc[q0 + 7], wloc[7], a1);
                    bval += a0 + a1;
                }
                ((float*)&s.w[base + lane])[r] = wmine;
                const int nbase = ((blk + 1) & 7) * 32;  // next panel's diag cols
#pragma unroll
                for (int q = 0; q < 32; q++)
                    dc[q] = g_D11T[(size_t)(nbase + q) * NVDIM + (nbase + lane)];
                if (later) {                    // solver warps fetch pc late
#pragma unroll
                    for (int g2 = 0; g2 < 8; g2++)
                        pc[g2] = g_D11P[(blk * 8 + g2) * NVDIM + j];
                }
            }
            __syncthreads();

            if (later) {                         // rank-32 off-diagonal update
#pragma unroll
                for (int g2 = 0; g2 < 8; g2++) {
                    const float2* wp = (const float2*)&s.w[base + 4 * g2];
                    float2 w0 = wp[0 + h], w1 = wp[2 + h], w2 = wp[4 + h], w3 = wp[6 + h];
                    ba0 = fmaf(pc[g2].x, w0.x, ba0); ba1 = fmaf(pc[g2].x, w0.y, ba1);
                    ba0 = fmaf(pc[g2].y, w1.x, ba0); ba1 = fmaf(pc[g2].y, w1.y, ba1);
                    ba0 = fmaf(pc[g2].z, w2.x, ba0); ba1 = fmaf(pc[g2].z, w2.y, ba1);
                    ba0 = fmaf(pc[g2].w, w3.x, ba0); ba1 = fmaf(pc[g2].w, w3.y, ba1);
                }
            }
        }

        // ---- phase C: x1 and y, k-split over thread groups ----
        const int xj = tid & 127, xq = tid >> 7;      // 4 k-chunks
        float xa0, xa1, xa2, xa3;
        xa0 = xa1 = xa2 = xa3 = (xq == 0) ? bxr : 0.f;
#pragma unroll 4
        for (int i = 0; i < 8; i++) {                 // A: 32 k per chunk
            int k4 = xq * 8 + i;
            float4 c = g_AT4[k4 * NXDIM + xj];
            const float4* v = &xc[4 * k4];
            FMA4C(xa0, xa1, xa2, xa3, c.x, v[0]);
            FMA4C(xa0, xa1, xa2, xa3, c.y, v[1]);
            FMA4C(xa0, xa1, xa2, xa3, c.z, v[2]);
            FMA4C(xa0, xa1, xa2, xa3, c.w, v[3]);
        }
#pragma unroll 4
        for (int i = 0; i < 16; i++) {                // B1: 64 k per chunk
            int k4 = xq * 16 + i;
            float4 c = g_B1T4[k4 * NXDIM + xj];
            const float4* v = &s.w[4 * k4];
            FMA4C(xa0, xa1, xa2, xa3, c.x, v[0]);
            FMA4C(xa0, xa1, xa2, xa3, c.y, v[1]);
            FMA4C(xa0, xa1, xa2, xa3, c.z, v[2]);
            FMA4C(xa0, xa1, xa2, xa3, c.w, v[3]);
        }
#pragma unroll
        for (int i = 0; i < 4; i++) {                 // B2: 16 k per chunk
            int k4 = xq * 4 + i;
            float4 c = g_B2T4[k4 * NXDIM + xj];
            const float4* v = &uc[4 * k4];
            FMA4C(xa0, xa1, xa2, xa3, c.x, v[0]);
            FMA4C(xa0, xa1, xa2, xa3, c.y, v[1]);
            FMA4C(xa0, xa1, xa2, xa3, c.z, v[2]);
            FMA4C(xa0, xa1, xa2, xa3, c.w, v[3]);
        }
        if (xq > 0) s.xpart[xq - 1][xj] = make_float4(xa0, xa1, xa2, xa3);

        const int yj = tid & 63, yq = tid >> 6;       // 8 k-chunks
        float ya0, ya1, ya2, ya3;
        ya0 = ya1 = ya2 = ya3 = (yq == 0) ? byr : 0.f;
#pragma unroll
        for (int i = 0; i < 4; i++) {                 // C2: 16 k per chunk
            int k4 = yq * 4 + i;
            float4 c = g_C2T4[k4 * NYDIM + yj];
            const float4* v = &xc[4 * k4];
            FMA4C(ya0, ya1, ya2, ya3, c.x, v[0]);
            FMA4C(ya0, ya1, ya2, ya3, c.y, v[1]);
            FMA4C(ya0, ya1, ya2, ya3, c.z, v[2]);
            FMA4C(ya0, ya1, ya2, ya3, c.w, v[3]);
        }
#pragma unroll 4
        for (int i = 0; i < 8; i++) {                 // D21: 32 k per chunk
            int k4 = yq * 8 + i;
            float4 c = g_D21T4[k4 * NYDIM + yj];
            const float4* v = &s.w[4 * k4];
            FMA4C(ya0, ya1, ya2, ya3, c.x, v[0]);
            FMA4C(ya0, ya1, ya2, ya3, c.y, v[1]);
            FMA4C(ya0, ya1, ya2, ya3, c.z, v[2]);
            FMA4C(ya0, ya1, ya2, ya3, c.w, v[3]);
        }
#pragma unroll
        for (int i = 0; i < 2; i++) {                 // D22: 8 k per chunk
            int k4 = yq * 2 + i;
            float4 c = g_D22T4[k4 * NYDIM + yj];
            const float4* v = &uc[4 * k4];
            FMA4C(ya0, ya1, ya2, ya3, c.x, v[0]);
            FMA4C(ya0, ya1, ya2, ya3, c.y, v[1]);
            FMA4C(ya0, ya1, ya2, ya3, c.z, v[2]);
            FMA4C(ya0, ya1, ya2, ya3, c.w, v[3]);
        }
        if (yq > 0) s.ypart[yq - 1][yj] = make_float4(ya0, ya1, ya2, ya3);
        __syncthreads();

        // ---- combines ----
        if (xq == 0) {
#pragma unroll
            for (int p = 0; p < 3; p++) {
                float4 pp = s.xpart[p][xj];
                xa0 += pp.x; xa1 += pp.y; xa2 += pp.z; xa3 += pp.w;
            }
            s.xk[nxt][xj] = make_float4(xa0, xa1, xa2, xa3);
        }
        if (yq == 0) {
#pragma unroll
            for (int p = 0; p < 7; p++) {
                float4 pp = s.ypart[p][yj];
                ya0 += pp.x; ya1 += pp.y; ya2 += pp.z; ya3 += pp.w;
            }
            float* yo = yout + ((size_t)t * BATCH + row0) * NYDIM + yj;
            yo[0 * NYDIM] = ya0;
            yo[1 * NYDIM] = ya1;
            yo[2 * NYDIM] = ya2;
            yo[3 * NYDIM] = ya3;
        }
        cur ^= 1;
    }

    // ---- final state x1 ----
    __syncthreads();
    if (tid < NXDIM) {
        float4 v = s.xk[cur][tid];
        out[(size_t)(row0 + 0) * NXDIM + tid] = v.x;
        out[(size_t)(row0 + 1) * NXDIM + tid] = v.y;
        out[(size_t)(row0 + 2) * NXDIM + tid] = v.z;
        out[(size_t)(row0 + 3) * NXDIM + tid] = v.w;
    }
}

extern "C" void kernel_launch(void* const* d_in, const int* in_sizes, int n_in,
                              void* d_out, int out_size)
{
    const float* x0  = (const float*)d_in[0];
    const float* u   = (const float*)d_in[1];
    const float* A   = (const float*)d_in[2];
    const float* B1  = (const float*)d_in[3];
    const float* B2  = (const float*)d_in[4];
    const float* C1  = (const float*)d_in[5];
    const float* C2  = (const float*)d_in[6];
    const float* D11 = (const float*)d_in[7];
    const float* D12 = (const float*)d_in[8];
    const float* D21 = (const float*)d_in[9];
    const float* D22 = (const float*)d_in[10];
    const float* bx  = (const float*)d_in[11];
    const float* bv  = (const float*)d_in[12];
    const float* by  = (const float*)d_in[13];
    float* out = (float*)d_out;

    prep_kernel<<<452, 256>>>(A, B1, B2, C1, C2, D11, D12, D21, D22);

    size_t smem = sizeof(Smem);
    cudaFuncSetAttribute(ren_kernel, cudaFuncAttributeMaxDynamicSharedMemorySize,
                         (int)smem);
    ren_kernel<<<NCTA, NTHR, smem>>>(x0, u, D11, bx, bv, by, out);
}